// round 5
// baseline (speedup 1.0000x reference)
#include <cuda_runtime.h>

// MaxLocaldist: per output pixel, max pairwise L2 distance among the 9 RGB
// pixels of the 3x3 neighborhood. Input (32,3,224,224) f32 NCHW.
// Output (32,1,224,224) f32, 1-pixel zero border.
//
// Column-pair decomposition + temporal d2 caching + packed f32x2 (as R4).
// R5: R_ROWS=14 -> grid=512 blocks < n_conc=592 (regs=64, 4 blocks/SM) so the
// whole kernel runs in a SINGLE wave (R4's 896-block grid ran 2 waves with a
// 51%-full tail), and the ~3-row-equivalent prologue is amortized over 14 rows.

#define HD 224
#define WD 224
#define HWD (HD * WD)
#define R_ROWS 14
#define FULLMASK 0xffffffffu

typedef unsigned long long u64;

__device__ __forceinline__ u64 bcast2(float v) {
    u64 r; asm("mov.b64 %0, {%1, %1};" : "=l"(r) : "f"(v)); return r;
}
__device__ __forceinline__ u64 pack2(float lo, float hi) {
    u64 r; asm("mov.b64 %0, {%1, %2};" : "=l"(r) : "f"(lo), "f"(hi)); return r;
}
__device__ __forceinline__ void unpack2(float& lo, float& hi, u64 v) {
    asm("mov.b64 {%0, %1}, %2;" : "=f"(lo), "=f"(hi) : "l"(v));
}
__device__ __forceinline__ u64 fma2(u64 a, u64 b, u64 c) {
    u64 r; asm("fma.rn.f32x2 %0, %1, %2, %3;" : "=l"(r) : "l"(a), "l"(b), "l"(c));
    return r;
}
__device__ __forceinline__ u64 mul2(u64 a, u64 b) {
    u64 r; asm("mul.rn.f32x2 %0, %1, %2;" : "=l"(r) : "l"(a), "l"(b));
    return r;
}

// packed d2: per channel, diff = a - b (exact via fma(b,-1,a)), accumulate.
__device__ __forceinline__ u64 d2p(const u64 a[3], const u64 b[3], u64 neg1) {
    const u64 d0 = fma2(b[0], neg1, a[0]);
    const u64 d1 = fma2(b[1], neg1, a[1]);
    const u64 d2 = fma2(b[2], neg1, a[2]);
    u64 s = mul2(d2, d2);
    s = fma2(d1, d1, s);
    s = fma2(d0, d0, s);
    return s;
}

__device__ __forceinline__ float d2s(const float a[3], const float b[3]) {
    const float dx = a[0] - b[0];
    const float dy = a[1] - b[1];
    const float dz = a[2] - b[2];
    return fmaf(dx, dx, fmaf(dy, dy, dz * dz));
}

__global__ __launch_bounds__(256, 4) void maxlocaldist_kernel(
    const float* __restrict__ x, float* __restrict__ out)
{
    const int lane = threadIdx.x & 31;
    const int wgrp = threadIdx.x >> 5;
    const int b    = blockIdx.z;
    const int h0   = blockIdx.y * R_ROWS;
    const int c0   = wgrp * 30 + lane;

    const float* xb = x + (long)b * 3 * HWD;

    int col[3];
#pragma unroll
    for (int j = 0; j < 3; j++) col[j] = min(c0 + j, WD - 1);

    u64 neg1; { float m1 = -1.0f; neg1 = bcast2(m1); }

    // window state: a = col0 scalar per slot/channel; bp = packed (col1,col2)
    float a[3][3];
    u64   bp[3][3];

#pragma unroll
    for (int s = 0; s < 3; s++) {
        const int r = min(max(h0 - 1 + s, 0), HD - 1);
#pragma unroll
        for (int ch = 0; ch < 3; ch++) {
            const float* row = xb + ch * HWD + r * WD;
            a[s][ch]  = __ldg(row + col[0]);
            bp[s][ch] = pack2(__ldg(row + col[1]), __ldg(row + col[2]));
        }
    }

    // packed d2 cache: Dp[slot_col0][slot_col12] = (D01, D02)
    u64 Dp[3][3];
#pragma unroll
    for (int s = 0; s < 3; s++) {
        u64 ab[3] = { bcast2(a[s][0]), bcast2(a[s][1]), bcast2(a[s][2]) };
#pragma unroll
        for (int c = 0; c < 3; c++)
            Dp[s][c] = d2p(ab, bp[c], neg1);
    }

    float sd[3];
    sd[2] = d2s(a[0], a[1]);
    sd[1] = d2s(a[0], a[2]);
    sd[0] = d2s(a[1], a[2]);

    const int  w_out   = c0 + 1;
    const bool wvalid  = (lane < 30) && (w_out <= WD - 1);
    const bool zerocol = (wgrp == 0) && (lane == 31);

#pragma unroll
    for (int rr = 0; rr < R_ROWS; rr++) {
        const int h = h0 + rr;

        const float S = fmaxf(fmaxf(sd[0], sd[1]), sd[2]);

        float P01, P02;
        {
            float lo, hi;
            unpack2(P01, P02, Dp[0][0]);
#pragma unroll
            for (int s = 0; s < 3; s++)
#pragma unroll
                for (int c = 0; c < 3; c++)
                    if (s | c) {
                        unpack2(lo, hi, Dp[s][c]);
                        P01 = fmaxf(P01, lo);
                        P02 = fmaxf(P02, hi);
                    }
        }

        const float S1 = __shfl_down_sync(FULLMASK, S,   1);
        const float S2 = __shfl_down_sync(FULLMASK, S,   2);
        const float Q  = __shfl_down_sync(FULLMASK, P01, 1);

        const float m = fmaxf(fmaxf(fmaxf(S, S1), fmaxf(S2, P01)),
                              fmaxf(Q, P02));
        float v;
        asm("sqrt.approx.f32 %0, %1;" : "=f"(v) : "f"(m));

        const bool border = (h == 0) || (h == HD - 1) || (w_out == WD - 1);
        if (wvalid)
            out[((long)b * HD + h) * WD + w_out] = border ? 0.0f : v;
        if (zerocol)
            out[((long)b * HD + h) * WD] = 0.0f;

        // slide window + incremental cache refresh
        if (rr < R_ROWS - 1) {
            const int X  = rr % 3;
            const int a1 = (rr + 1) % 3;
            const int a2 = (rr + 2) % 3;
            const int rn = min(h + 2, HD - 1);

#pragma unroll
            for (int ch = 0; ch < 3; ch++) {
                const float* row = xb + ch * HWD + rn * WD;
                a[X][ch]  = __ldg(row + col[0]);
                bp[X][ch] = pack2(__ldg(row + col[1]), __ldg(row + col[2]));
            }

            {
                u64 abX[3] = { bcast2(a[X][0]), bcast2(a[X][1]), bcast2(a[X][2]) };
#pragma unroll
                for (int c = 0; c < 3; c++)
                    Dp[X][c] = d2p(abX, bp[c], neg1);

                // sd: new col0 row X vs old col0 rows a1, a2 (packed pair)
                u64 q[3] = { pack2(a[a1][0], a[a2][0]),
                             pack2(a[a1][1], a[a2][1]),
                             pack2(a[a1][2], a[a2][2]) };
                const u64 sdp = d2p(abX, q, neg1);
                unpack2(sd[a2], sd[a1], sdp);
            }
            {
                u64 abA1[3] = { bcast2(a[a1][0]), bcast2(a[a1][1]), bcast2(a[a1][2]) };
                Dp[a1][X] = d2p(abA1, bp[X], neg1);
            }
            {
                u64 abA2[3] = { bcast2(a[a2][0]), bcast2(a[a2][1]), bcast2(a[a2][2]) };
                Dp[a2][X] = d2p(abA2, bp[X], neg1);
            }
        }
    }
}

extern "C" void kernel_launch(void* const* d_in, const int* in_sizes, int n_in,
                              void* d_out, int out_size)
{
    const float* x = (const float*)d_in[0];
    float* out = (float*)d_out;

    dim3 block(256, 1, 1);
    dim3 grid(1, HD / R_ROWS, 32);   // 16 row-tiles x 32 batches = 512 blocks
    maxlocaldist_kernel<<<grid, block>>>(x, out);
}